// round 4
// baseline (speedup 1.0000x reference)
#include <cuda_runtime.h>
#include <math.h>

// x: (4, 192, 256, 256) fp32, WS=8, shift=4, NHEADS=4, HD=48, nW=4096, T=64
// 384 threads/CTA, 1 window/CTA. All buffers stride 192 (float4-aligned).
#define OFF_X 0          // w0 / w1 residual   64x192 = 12288 f
#define OFF_Q 12288      // q -> o-concat      64x192
#define OFF_K 24576      // k -> H (LN2 out)   64x192
#define OFF_V 36864      // v -> G (gelu out)  64x192
#define OFF_P 49152      // scores 64x64 -> output staging chunk (4096 f)
#define OFF_W 53248      // weight stage 24x192 = 4608 f
#define SMEM_FLOATS 57856
#define SMEM_BYTES (SMEM_FLOATS * 4)   // 231424 B

__device__ __forceinline__ void stage_w(float* __restrict__ sm,
                                        const float* __restrict__ w,
                                        int wldf, int col0, int k0, int tid)
{
    #pragma unroll
    for (int it = 0; it < 3; it++) {
        const int l  = tid + it * 384;       // 0..1151 float4s
        const int kk = l / 48;
        const int j4 = l - kk * 48;
        *(float4*)&sm[OFF_W + l * 4] =
            *(const float4*)&w[(size_t)(k0 + kk) * wldf + col0 + j4 * 4];
    }
}

__device__ __forceinline__ void gemm_ktile(const float* __restrict__ sA,
                                           const float* __restrict__ sW,
                                           int r0, int c0, int k0,
                                           float (&acc)[4][8])
{
    #pragma unroll
    for (int kk4 = 0; kk4 < 6; kk4++) {
        float a[4][4];
        #pragma unroll
        for (int i = 0; i < 4; i++)
            *(float4*)a[i] = *(const float4*)&sA[(r0 + i) * 192 + k0 + kk4 * 4];
        #pragma unroll
        for (int kk = 0; kk < 4; kk++) {
            float w[8];
            *(float4*)&w[0] = *(const float4*)&sW[(kk4 * 4 + kk) * 192 + c0];
            *(float4*)&w[4] = *(const float4*)&sW[(kk4 * 4 + kk) * 192 + c0 + 4];
            #pragma unroll
            for (int i = 0; i < 4; i++)
                #pragma unroll
                for (int j = 0; j < 8; j++)
                    acc[i][j] = fmaf(a[i][kk], w[j], acc[i][j]);
        }
    }
}

// full 192-deep GEMM: acc += sA(64x192) @ w[k, col0 + 0..191]
__device__ __forceinline__ void gemm_192(float* __restrict__ sm,
                                         const float* __restrict__ sA,
                                         const float* __restrict__ w,
                                         int wldf, int col0,
                                         int tid, int r0, int c0,
                                         float (&acc)[4][8])
{
    for (int k0 = 0; k0 < 192; k0 += 24) {
        stage_w(sm, w, wldf, col0, k0, tid);
        __syncthreads();
        gemm_ktile(sA, &sm[OFF_W], r0, c0, k0, acc);
        __syncthreads();
    }
}

__global__ __launch_bounds__(384, 1)
void swin_block_kernel(const float* __restrict__ x,
                       const float* __restrict__ g1,  const float* __restrict__ b1,
                       const float* __restrict__ wqkv,const float* __restrict__ bqkv,
                       const float* __restrict__ wo,  const float* __restrict__ bo,
                       const float* __restrict__ g2,  const float* __restrict__ b2,
                       const float* __restrict__ wm1, const float* __restrict__ bm1,
                       const float* __restrict__ wm2, const float* __restrict__ bm2,
                       float* __restrict__ out)
{
    extern __shared__ float sm[];
    const int tid = threadIdx.x;
    const int wi  = blockIdx.x;
    const int b   = wi >> 10;
    const int hb  = (wi >> 5) & 31;
    const int wb  = wi & 31;

    // ---------------- gather window (shift folded), float4 global loads ----------------
    for (int l = tid; l < 3072; l += 384) {
        const int c    = l >> 4;
        const int r    = l & 15;
        const int ty   = r >> 1, half = r & 1;
        const int sh   = (hb * 8 + ty + 4) & 255;
        const int sw   = (wb * 8 + half * 4 + 4) & 255;
        const float4 v = *(const float4*)&x[(((size_t)(b * 192 + c)) << 16) + (sh << 8) + sw];
        float* dst = &sm[OFF_X + (ty * 8 + half * 4) * 192 + c];
        dst[0] = v.x; dst[192] = v.y; dst[384] = v.z; dst[576] = v.w;
    }
    __syncthreads();

    // ---------------- LN1 in place (4 threads/token) ----------------
    if (tid < 256) {
        const int t = tid >> 2, qd = tid & 3;
        float* row = &sm[OFF_X + t * 192 + qd * 48];
        float s = 0.f, s2 = 0.f;
        #pragma unroll
        for (int j4 = 0; j4 < 12; j4++) {
            const float4 v = *(const float4*)&row[j4 * 4];
            s += v.x + v.y + v.z + v.w;
            s2 += v.x * v.x + v.y * v.y + v.z * v.z + v.w * v.w;
        }
        s  += __shfl_xor_sync(0xffffffffu, s, 1);
        s2 += __shfl_xor_sync(0xffffffffu, s2, 1);
        s  += __shfl_xor_sync(0xffffffffu, s, 2);
        s2 += __shfl_xor_sync(0xffffffffu, s2, 2);
        const float mean = s * (1.f / 192.f);
        const float var  = s2 * (1.f / 192.f) - mean * mean;
        const float rstd = rsqrtf(var + 1e-5f);
        #pragma unroll
        for (int j4 = 0; j4 < 12; j4++) {
            float4 v  = *(const float4*)&row[j4 * 4];
            const float4 gg = *(const float4*)&g1[qd * 48 + j4 * 4];
            const float4 bb = *(const float4*)&b1[qd * 48 + j4 * 4];
            v.x = (v.x - mean) * rstd * gg.x + bb.x;
            v.y = (v.y - mean) * rstd * gg.y + bb.y;
            v.z = (v.z - mean) * rstd * gg.z + bb.z;
            v.w = (v.w - mean) * rstd * gg.w + bb.w;
            *(float4*)&row[j4 * 4] = v;
        }
    }
    __syncthreads();

    const int r0 = (tid & 15) * 4;     // 16 row groups of 4
    const int c0 = (tid >> 4) * 8;     // 24 col groups of 8

    // ---------------- q / k / v GEMMs (each 64x192 @ 192x192) ----------------
    #pragma unroll 1
    for (int p = 0; p < 3; p++) {
        float acc[4][8];
        #pragma unroll
        for (int i = 0; i < 4; i++)
            #pragma unroll
            for (int j = 0; j < 8; j++) acc[i][j] = 0.f;
        gemm_192(sm, &sm[OFF_X], wqkv, 576, p * 192, tid, r0, c0, acc);
        float bb[8];
        *(float4*)&bb[0] = *(const float4*)&bqkv[p * 192 + c0];
        *(float4*)&bb[4] = *(const float4*)&bqkv[p * 192 + c0 + 4];
        const int offp = (p == 0) ? OFF_Q : (p == 1) ? OFF_K : OFF_V;
        #pragma unroll
        for (int i = 0; i < 4; i++) {
            float4 v0 = {acc[i][0]+bb[0], acc[i][1]+bb[1], acc[i][2]+bb[2], acc[i][3]+bb[3]};
            float4 v1 = {acc[i][4]+bb[4], acc[i][5]+bb[5], acc[i][6]+bb[6], acc[i][7]+bb[7]};
            *(float4*)&sm[offp + (r0 + i) * 192 + c0]     = v0;
            *(float4*)&sm[offp + (r0 + i) * 192 + c0 + 4] = v1;
        }
    }
    __syncthreads();

    // ---------------- attention, per head; o written into Q slab in place ----------------
    for (int h = 0; h < 4; h++) {
        if (tid < 256) {           // scores: Q_h @ K_h^T via row-major dot products
            const int rs0 = (tid >> 4) * 4, cs0 = (tid & 15) * 4;
            const float* qp = &sm[OFF_Q + h * 48];
            const float* kp = &sm[OFF_K + h * 48];
            float sc[4][4];
            #pragma unroll
            for (int i = 0; i < 4; i++)
                #pragma unroll
                for (int j = 0; j < 4; j++) sc[i][j] = 0.f;
            #pragma unroll
            for (int k4 = 0; k4 < 12; k4++) {
                float qa[4][4], kb[4][4];
                #pragma unroll
                for (int i = 0; i < 4; i++)
                    *(float4*)qa[i] = *(const float4*)&qp[(rs0 + i) * 192 + k4 * 4];
                #pragma unroll
                for (int j = 0; j < 4; j++)
                    *(float4*)kb[j] = *(const float4*)&kp[(cs0 + j) * 192 + k4 * 4];
                #pragma unroll
                for (int i = 0; i < 4; i++)
                    #pragma unroll
                    for (int j = 0; j < 4; j++)
                        #pragma unroll
                        for (int kk = 0; kk < 4; kk++)
                            sc[i][j] = fmaf(qa[i][kk], kb[j][kk], sc[i][j]);
            }
            const float scale = 0.14433756729740643f;   // 1/sqrt(48)
            #pragma unroll
            for (int i = 0; i < 4; i++) {
                float4 v = {sc[i][0]*scale, sc[i][1]*scale, sc[i][2]*scale, sc[i][3]*scale};
                *(float4*)&sm[OFF_P + (rs0 + i) * 64 + cs0] = v;
            }
        }
        __syncthreads();

        if (tid < 256) {           // softmax over 64 keys (4 threads/row)
            const int t = tid >> 2, qd = tid & 3;
            float* pr = &sm[OFF_P + t * 64 + qd * 16];
            float m = -1e30f;
            #pragma unroll
            for (int j = 0; j < 16; j++) m = fmaxf(m, pr[j]);
            m = fmaxf(m, __shfl_xor_sync(0xffffffffu, m, 1));
            m = fmaxf(m, __shfl_xor_sync(0xffffffffu, m, 2));
            float s = 0.f;
            #pragma unroll
            for (int j = 0; j < 16; j++) { const float e = __expf(pr[j] - m); pr[j] = e; s += e; }
            s += __shfl_xor_sync(0xffffffffu, s, 1);
            s += __shfl_xor_sync(0xffffffffu, s, 2);
            const float inv = 1.f / s;
            #pragma unroll
            for (int j = 0; j < 16; j++) pr[j] *= inv;
        }
        __syncthreads();

        if (tid < 256) {           // AV: P(64x64) @ V_h(64x48) -> Q slab [, h*48..)
            const int rs0 = (tid >> 4) * 4, cv0 = (tid & 15) * 3;
            float ao[4][3];
            #pragma unroll
            for (int i = 0; i < 4; i++)
                #pragma unroll
                for (int j = 0; j < 3; j++) ao[i][j] = 0.f;
            #pragma unroll
            for (int k4 = 0; k4 < 16; k4++) {
                float pa[4][4];
                #pragma unroll
                for (int i = 0; i < 4; i++)
                    *(float4*)pa[i] = *(const float4*)&sm[OFF_P + (rs0 + i) * 64 + k4 * 4];
                #pragma unroll
                for (int kk = 0; kk < 4; kk++) {
                    float vv[3];
                    #pragma unroll
                    for (int j = 0; j < 3; j++)
                        vv[j] = sm[OFF_V + (k4 * 4 + kk) * 192 + h * 48 + cv0 + j];
                    #pragma unroll
                    for (int i = 0; i < 4; i++)
                        #pragma unroll
                        for (int j = 0; j < 3; j++)
                            ao[i][j] = fmaf(pa[i][kk], vv[j], ao[i][j]);
                }
            }
            #pragma unroll
            for (int i = 0; i < 4; i++)
                #pragma unroll
                for (int j = 0; j < 3; j++)
                    sm[OFF_Q + (rs0 + i) * 192 + h * 48 + cv0 + j] = ao[i][j];
        }
        __syncthreads();
    }

    // ---------------- o-proj + residual into X ----------------
    {
        float acc[4][8];
        #pragma unroll
        for (int i = 0; i < 4; i++)
            #pragma unroll
            for (int j = 0; j < 8; j++) acc[i][j] = 0.f;
        gemm_192(sm, &sm[OFF_Q], wo, 192, 0, tid, r0, c0, acc);
        float bb[8];
        *(float4*)&bb[0] = *(const float4*)&bo[c0];
        *(float4*)&bb[4] = *(const float4*)&bo[c0 + 4];
        #pragma unroll
        for (int i = 0; i < 4; i++) {
            float4 x0 = *(const float4*)&sm[OFF_X + (r0 + i) * 192 + c0];
            float4 x1 = *(const float4*)&sm[OFF_X + (r0 + i) * 192 + c0 + 4];
            x0.x += acc[i][0]+bb[0]; x0.y += acc[i][1]+bb[1];
            x0.z += acc[i][2]+bb[2]; x0.w += acc[i][3]+bb[3];
            x1.x += acc[i][4]+bb[4]; x1.y += acc[i][5]+bb[5];
            x1.z += acc[i][6]+bb[6]; x1.w += acc[i][7]+bb[7];
            *(float4*)&sm[OFF_X + (r0 + i) * 192 + c0]     = x0;
            *(float4*)&sm[OFF_X + (r0 + i) * 192 + c0 + 4] = x1;
        }
    }
    __syncthreads();

    // ---------------- LN2: X -> H (K region) ----------------
    if (tid < 256) {
        const int t = tid >> 2, qd = tid & 3;
        const float* row = &sm[OFF_X + t * 192 + qd * 48];
        float* hrow = &sm[OFF_K + t * 192 + qd * 48];
        float s = 0.f, s2 = 0.f;
        #pragma unroll
        for (int j4 = 0; j4 < 12; j4++) {
            const float4 v = *(const float4*)&row[j4 * 4];
            s += v.x + v.y + v.z + v.w;
            s2 += v.x * v.x + v.y * v.y + v.z * v.z + v.w * v.w;
        }
        s  += __shfl_xor_sync(0xffffffffu, s, 1);
        s2 += __shfl_xor_sync(0xffffffffu, s2, 1);
        s  += __shfl_xor_sync(0xffffffffu, s, 2);
        s2 += __shfl_xor_sync(0xffffffffu, s2, 2);
        const float mean = s * (1.f / 192.f);
        const float var  = s2 * (1.f / 192.f) - mean * mean;
        const float rstd = rsqrtf(var + 1e-5f);
        #pragma unroll
        for (int j4 = 0; j4 < 12; j4++) {
            float4 v  = *(const float4*)&row[j4 * 4];
            const float4 gg = *(const float4*)&g2[qd * 48 + j4 * 4];
            const float4 bb = *(const float4*)&b2[qd * 48 + j4 * 4];
            v.x = (v.x - mean) * rstd * gg.x + bb.x;
            v.y = (v.y - mean) * rstd * gg.y + bb.y;
            v.z = (v.z - mean) * rstd * gg.z + bb.z;
            v.w = (v.w - mean) * rstd * gg.w + bb.w;
            *(float4*)&hrow[j4 * 4] = v;
        }
    }
    __syncthreads();

    // ---------------- MLP: 4 slabs of 192 hidden ----------------
    float acc2[4][8];
    #pragma unroll
    for (int i = 0; i < 4; i++)
        #pragma unroll
        for (int j = 0; j < 8; j++) acc2[i][j] = 0.f;

    #pragma unroll 1
    for (int jt = 0; jt < 4; jt++) {
        float acc1[4][8];
        #pragma unroll
        for (int i = 0; i < 4; i++)
            #pragma unroll
            for (int j = 0; j < 8; j++) acc1[i][j] = 0.f;
        gemm_192(sm, &sm[OFF_K], wm1, 768, jt * 192, tid, r0, c0, acc1);
        // bias + exact gelu -> G (V region)
        float bb[8];
        *(float4*)&bb[0] = *(const float4*)&bm1[jt * 192 + c0];
        *(float4*)&bb[4] = *(const float4*)&bm1[jt * 192 + c0 + 4];
        #pragma unroll
        for (int i = 0; i < 4; i++) {
            float g[8];
            #pragma unroll
            for (int j = 0; j < 8; j++) {
                const float v = acc1[i][j] + bb[j];
                g[j] = 0.5f * v * (1.f + erff(v * 0.70710678118654752f));
            }
            *(float4*)&sm[OFF_V + (r0 + i) * 192 + c0]     = *(float4*)&g[0];
            *(float4*)&sm[OFF_V + (r0 + i) * 192 + c0 + 4] = *(float4*)&g[4];
        }
        // acc2 += G @ W2[jt*192 .. jt*192+192, :]   (stage_w's sync orders G writes)
        gemm_192(sm, &sm[OFF_V], wm2 + (size_t)jt * 192 * 192, 192, 0, tid, r0, c0, acc2);
    }

    // ---------------- residual + staged scatter (3 chunks of 64 cols) ----------------
    const int mychunk = c0 >> 6;
    for (int ch = 0; ch < 3; ch++) {
        __syncthreads();
        if (ch == mychunk) {
            float bb[8];
            *(float4*)&bb[0] = *(const float4*)&bm2[c0];
            *(float4*)&bb[4] = *(const float4*)&bm2[c0 + 4];
            #pragma unroll
            for (int i = 0; i < 4; i++) {
                #pragma unroll
                for (int j = 0; j < 8; j++) {
                    const int c = c0 + j;
                    const float v = acc2[i][j] + bb[j] + sm[OFF_X + (r0 + i) * 192 + c];
                    sm[OFF_P + (c & 63) * 64 + (r0 + i)] = v;
                }
            }
        }
        __syncthreads();
        for (int l = tid; l < 1024; l += 384) {
            const int cl = l >> 4;
            const int r  = l & 15;
            const int ty = r >> 1, half = r & 1;
            const int c  = ch * 64 + cl;
            const int sh = (hb * 8 + ty + 4) & 255;
            const int sw = (wb * 8 + half * 4 + 4) & 255;
            const float4 v = *(const float4*)&sm[OFF_P + cl * 64 + ty * 8 + half * 4];
            *(float4*)&out[(((size_t)(b * 192 + c)) << 16) + (sh << 8) + sw] = v;
        }
    }
}

extern "C" void kernel_launch(void* const* d_in, const int* in_sizes, int n_in,
                              void* d_out, int out_size)
{
    (void)in_sizes; (void)n_in; (void)out_size;
    const float* x    = (const float*)d_in[0];
    const float* g1   = (const float*)d_in[1];
    const float* b1   = (const float*)d_in[2];
    const float* wqkv = (const float*)d_in[3];
    const float* bqkv = (const float*)d_in[4];
    const float* wo   = (const float*)d_in[5];
    const float* bo   = (const float*)d_in[6];
    const float* g2   = (const float*)d_in[7];
    const float* b2   = (const float*)d_in[8];
    const float* wm1  = (const float*)d_in[9];
    const float* bm1  = (const float*)d_in[10];
    const float* wm2  = (const float*)d_in[11];
    const float* bm2  = (const float*)d_in[12];
    float* out = (float*)d_out;

    cudaFuncSetAttribute(swin_block_kernel,
                         cudaFuncAttributeMaxDynamicSharedMemorySize, SMEM_BYTES);
    swin_block_kernel<<<4096, 384, SMEM_BYTES>>>(
        x, g1, b1, wqkv, bqkv, wo, bo, g2, b2, wm1, bm1, wm2, bm2, out);
}

// round 5
// speedup vs baseline: 4.2034x; 4.2034x over previous
#include <cuda_runtime.h>
#include <math.h>

// x: (4, 192, 256, 256) fp32, WS=8, shift=4, NHEADS=4, HD=48, nW=4096, T=64
// 384 threads/CTA, 1 window/CTA.
// Layout rules (bank-conflict-free):
//  - t-major buffers (stride 192): written by GEMM epilogues (lanes = cols, contiguous)
//  - c-major buffers (stride 68): written/read token-parallel (lanes = tokens, contiguous)
//  - P / staging: stride 65, scalar access
#define XS 68
#define PS 65
#define OFF_X 0          // X residual, c-major 192*68 = 13056 f
#define OFF_K 13056      // K c-major -> H2 (LN2 out) c-major, 13056 f
#define OFF_Q 26112      // Q t-major -> O concat, 12288 f
#define OFF_V 38400      // V t-major -> G (gelu out), 12288 f
#define OFF_P 50688      // 64*65 = 4160 f (scores / LN scratch / out staging)
#define OFF_W 54848      // weight stage 16*192 = 3072 f
#define SMEM_FLOATS 57920
#define SMEM_BYTES (SMEM_FLOATS * 4)   // 231680 B

// full 192-deep GEMM: acc[4][8] += A(64x192) @ w[:, col0 + {c0..c0+3, c0+96..c0+99}]
// AMODE 0: A c-major stride XS (broadcast float4 = 4 rows at one channel)
// AMODE 1: A t-major stride 192 (broadcast float4 = 4 channels of one row)
template<int AMODE>
__device__ __forceinline__ void gemm_full(float* __restrict__ sm,
                                          const float* __restrict__ sA,
                                          const float* __restrict__ w,
                                          int wldf, int col0,
                                          int tid, int r0, int c0,
                                          float (&acc)[4][8])
{
    for (int k0 = 0; k0 < 192; k0 += 16) {
        #pragma unroll
        for (int it = 0; it < 2; it++) {
            const int l  = tid + it * 384;      // 0..767 float4s (16 rows x 48)
            const int kk = l / 48;
            const int j4 = l - kk * 48;
            *(float4*)&sm[OFF_W + kk * 192 + j4 * 4] =
                *(const float4*)&w[(size_t)(k0 + kk) * wldf + col0 + j4 * 4];
        }
        __syncthreads();
        const float* sW = &sm[OFF_W];
        #pragma unroll
        for (int kk4 = 0; kk4 < 4; kk4++) {
            float a[4][4];                      // a[kk][i] = A[row r0+i][k0+kk4*4+kk]
            if (AMODE == 0) {
                #pragma unroll
                for (int kk = 0; kk < 4; kk++)
                    *(float4*)a[kk] = *(const float4*)&sA[(k0 + kk4 * 4 + kk) * XS + r0];
            } else {
                float at[4][4];
                #pragma unroll
                for (int i = 0; i < 4; i++)
                    *(float4*)at[i] = *(const float4*)&sA[(r0 + i) * 192 + k0 + kk4 * 4];
                #pragma unroll
                for (int kk = 0; kk < 4; kk++)
                    #pragma unroll
                    for (int i = 0; i < 4; i++)
                        a[kk][i] = at[i][kk];
            }
            #pragma unroll
            for (int kk = 0; kk < 4; kk++) {
                float wv[8];
                *(float4*)&wv[0] = *(const float4*)&sW[(kk4 * 4 + kk) * 192 + c0];
                *(float4*)&wv[4] = *(const float4*)&sW[(kk4 * 4 + kk) * 192 + c0 + 96];
                #pragma unroll
                for (int j = 0; j < 8; j++)
                    #pragma unroll
                    for (int i = 0; i < 4; i++)
                        acc[i][j] = fmaf(a[kk][i], wv[j], acc[i][j]);
            }
        }
        __syncthreads();
    }
}

// token-parallel LayerNorm on c-major buffers: dst[c] = (src[c]-mu)*rstd*g[c]+b[c]
__device__ __forceinline__ void layernorm(float* __restrict__ sm,
                                          int src, int dst,
                                          const float* __restrict__ g,
                                          const float* __restrict__ bp,
                                          int tid)
{
    const int t = tid & 63, chk = tid >> 6;    // 6 chunks of 32 channels
    {
        float s = 0.f, s2 = 0.f;
        #pragma unroll 8
        for (int j = 0; j < 32; j++) {
            const float v = sm[src + (chk * 32 + j) * XS + t];
            s += v; s2 += v * v;
        }
        sm[OFF_P + chk * 64 + t]       = s;
        sm[OFF_P + 384 + chk * 64 + t] = s2;
    }
    __syncthreads();
    if (tid < 64) {
        float s = 0.f, s2 = 0.f;
        #pragma unroll
        for (int ch = 0; ch < 6; ch++) {
            s  += sm[OFF_P + ch * 64 + tid];
            s2 += sm[OFF_P + 384 + ch * 64 + tid];
        }
        const float mean = s * (1.f / 192.f);
        const float var  = s2 * (1.f / 192.f) - mean * mean;
        sm[OFF_P + 768 + tid] = mean;
        sm[OFF_P + 832 + tid] = rsqrtf(var + 1e-5f);
    }
    __syncthreads();
    {
        const float mean = sm[OFF_P + 768 + t];
        const float rstd = sm[OFF_P + 832 + t];
        #pragma unroll 8
        for (int j = 0; j < 32; j++) {
            const int c = chk * 32 + j;
            const float v = sm[src + c * XS + t];
            sm[dst + c * XS + t] = (v - mean) * rstd * g[c] + bp[c];
        }
    }
    __syncthreads();
}

__global__ __launch_bounds__(384, 1)
void swin_block_kernel(const float* __restrict__ x,
                       const float* __restrict__ g1,  const float* __restrict__ b1,
                       const float* __restrict__ wqkv,const float* __restrict__ bqkv,
                       const float* __restrict__ wo,  const float* __restrict__ bo,
                       const float* __restrict__ g2,  const float* __restrict__ b2,
                       const float* __restrict__ wm1, const float* __restrict__ bm1,
                       const float* __restrict__ wm2, const float* __restrict__ bm2,
                       float* __restrict__ out)
{
    extern __shared__ float sm[];
    const int tid = threadIdx.x;
    const int wi  = blockIdx.x;
    const int b   = wi >> 10;
    const int hb  = (wi >> 5) & 31;
    const int wb  = wi & 31;

    // ---- gather window into X (c-major), shift folded, coalesced float4 ----
    for (int l = tid; l < 3072; l += 384) {
        const int c    = l >> 4;
        const int r16  = l & 15;
        const int ty   = r16 >> 1, half = r16 & 1;
        const int sh   = (hb * 8 + ty + 4) & 255;
        const int sw   = (wb * 8 + half * 4 + 4) & 255;
        const float4 v = *(const float4*)&x[(((size_t)(b * 192 + c)) << 16) + (sh << 8) + sw];
        *(float4*)&sm[OFF_X + c * XS + ty * 8 + half * 4] = v;
    }
    __syncthreads();

    // ---- LN1 in place (residual base = LN1 output) ----
    layernorm(sm, OFF_X, OFF_X, g1, b1, tid);

    const int r0 = (tid / 24) * 4;     // 16 row groups of 4 (broadcast within lanes)
    const int c0 = (tid % 24) * 4;     // cols {c0..c0+3, c0+96..c0+99}

    // ---- q / k / v GEMMs ----
    #pragma unroll 1
    for (int p = 0; p < 3; p++) {
        float acc[4][8];
        #pragma unroll
        for (int i = 0; i < 4; i++)
            #pragma unroll
            for (int j = 0; j < 8; j++) acc[i][j] = 0.f;
        gemm_full<0>(sm, &sm[OFF_X], wqkv, 576, p * 192, tid, r0, c0, acc);
        float bb[8];
        #pragma unroll
        for (int j = 0; j < 4; j++) {
            bb[j]     = bqkv[p * 192 + c0 + j];
            bb[4 + j] = bqkv[p * 192 + c0 + 96 + j];
        }
        if (p == 1) {
            // K written c-major (stride XS) for conflict-free scores reads
            #pragma unroll
            for (int j = 0; j < 4; j++)
                #pragma unroll
                for (int i = 0; i < 4; i++) {
                    sm[OFF_K + (c0 + j) * XS + r0 + i]      = acc[i][j] + bb[j];
                    sm[OFF_K + (c0 + 96 + j) * XS + r0 + i] = acc[i][4 + j] + bb[4 + j];
                }
        } else {
            const int off = (p == 0) ? OFF_Q : OFF_V;
            #pragma unroll
            for (int i = 0; i < 4; i++) {
                float4 v0 = {acc[i][0]+bb[0], acc[i][1]+bb[1], acc[i][2]+bb[2], acc[i][3]+bb[3]};
                float4 v1 = {acc[i][4]+bb[4], acc[i][5]+bb[5], acc[i][6]+bb[6], acc[i][7]+bb[7]};
                *(float4*)&sm[off + (r0 + i) * 192 + c0]      = v0;
                *(float4*)&sm[off + (r0 + i) * 192 + c0 + 96] = v1;
            }
        }
    }
    __syncthreads();

    // ---- attention per head; O written into Q slab in place ----
    for (int h = 0; h < 4; h++) {
        if (tid < 256) {           // scores: Q(t-major, broadcast) x K(c-major, contiguous)
            const int rs0 = (tid >> 4) * 4, cs0 = (tid & 15) * 4;
            const float* qp = &sm[OFF_Q + h * 48];
            const float* kp = &sm[OFF_K + h * 48 * XS];
            float sc[4][4];
            #pragma unroll
            for (int i = 0; i < 4; i++)
                #pragma unroll
                for (int j = 0; j < 4; j++) sc[i][j] = 0.f;
            #pragma unroll 4
            for (int k4 = 0; k4 < 12; k4++) {
                float qa[4][4];
                #pragma unroll
                for (int i = 0; i < 4; i++)
                    *(float4*)qa[i] = *(const float4*)&qp[(rs0 + i) * 192 + k4 * 4];
                #pragma unroll
                for (int kk = 0; kk < 4; kk++) {
                    float kb[4];
                    *(float4*)kb = *(const float4*)&kp[(k4 * 4 + kk) * XS + cs0];
                    #pragma unroll
                    for (int i = 0; i < 4; i++)
                        #pragma unroll
                        for (int j = 0; j < 4; j++)
                            sc[i][j] = fmaf(qa[i][kk], kb[j], sc[i][j]);
                }
            }
            const float scale = 0.14433756729740643f;   // 1/sqrt(48)
            #pragma unroll
            for (int i = 0; i < 4; i++)
                #pragma unroll
                for (int j = 0; j < 4; j++)
                    sm[OFF_P + (rs0 + i) * PS + cs0 + j] = sc[i][j] * scale;
        }
        __syncthreads();

        if (tid < 256) {           // softmax over 64 keys (4 threads/row)
            const int t = tid >> 2, qd = tid & 3;
            float* pr = &sm[OFF_P + t * PS + qd * 16];
            float m = -1e30f;
            #pragma unroll
            for (int j = 0; j < 16; j++) m = fmaxf(m, pr[j]);
            m = fmaxf(m, __shfl_xor_sync(0xffffffffu, m, 1));
            m = fmaxf(m, __shfl_xor_sync(0xffffffffu, m, 2));
            float s = 0.f;
            #pragma unroll
            for (int j = 0; j < 16; j++) { const float e = __expf(pr[j] - m); pr[j] = e; s += e; }
            s += __shfl_xor_sync(0xffffffffu, s, 1);
            s += __shfl_xor_sync(0xffffffffu, s, 2);
            const float inv = 1.f / s;
            #pragma unroll
            for (int j = 0; j < 16; j++) pr[j] *= inv;
        }
        __syncthreads();

        if (tid < 256) {           // AV: P(broadcast) @ V_h -> Q slab cols [h*48, h*48+48)
            const int rs0 = (tid >> 4) * 4, cv0 = (tid & 15) * 3;
            float ao[4][3];
            #pragma unroll
            for (int i = 0; i < 4; i++)
                #pragma unroll
                for (int j = 0; j < 3; j++) ao[i][j] = 0.f;
            #pragma unroll 4
            for (int k = 0; k < 64; k++) {
                float pa[4];
                #pragma unroll
                for (int i = 0; i < 4; i++) pa[i] = sm[OFF_P + (rs0 + i) * PS + k];
                float vv[3];
                #pragma unroll
                for (int j = 0; j < 3; j++)
                    vv[j] = sm[OFF_V + k * 192 + h * 48 + cv0 + j];
                #pragma unroll
                for (int i = 0; i < 4; i++)
                    #pragma unroll
                    for (int j = 0; j < 3; j++)
                        ao[i][j] = fmaf(pa[i], vv[j], ao[i][j]);
            }
            #pragma unroll
            for (int i = 0; i < 4; i++)
                #pragma unroll
                for (int j = 0; j < 3; j++)
                    sm[OFF_Q + (rs0 + i) * 192 + h * 48 + cv0 + j] = ao[i][j];
        }
        __syncthreads();
    }

    // ---- o-proj + residual RMW into X (c-major, scalar) ----
    {
        float acc[4][8];
        #pragma unroll
        for (int i = 0; i < 4; i++)
            #pragma unroll
            for (int j = 0; j < 8; j++) acc[i][j] = 0.f;
        gemm_full<1>(sm, &sm[OFF_Q], wo, 192, 0, tid, r0, c0, acc);
        float bb[8];
        #pragma unroll
        for (int j = 0; j < 4; j++) { bb[j] = bo[c0 + j]; bb[4 + j] = bo[c0 + 96 + j]; }
        #pragma unroll
        for (int j = 0; j < 4; j++)
            #pragma unroll
            for (int i = 0; i < 4; i++) {
                sm[OFF_X + (c0 + j) * XS + r0 + i]      += acc[i][j] + bb[j];
                sm[OFF_X + (c0 + 96 + j) * XS + r0 + i] += acc[i][4 + j] + bb[4 + j];
            }
    }
    __syncthreads();

    // ---- LN2: X -> H2 (reuses K buffer, c-major) ----
    layernorm(sm, OFF_X, OFF_K, g2, b2, tid);

    // ---- MLP: 4 slabs of 192 hidden; G reuses V (t-major) ----
    float acc2[4][8];
    #pragma unroll
    for (int i = 0; i < 4; i++)
        #pragma unroll
        for (int j = 0; j < 8; j++) acc2[i][j] = 0.f;

    #pragma unroll 1
    for (int jt = 0; jt < 4; jt++) {
        float acc1[4][8];
        #pragma unroll
        for (int i = 0; i < 4; i++)
            #pragma unroll
            for (int j = 0; j < 8; j++) acc1[i][j] = 0.f;
        gemm_full<0>(sm, &sm[OFF_K], wm1, 768, jt * 192, tid, r0, c0, acc1);
        float bb[8];
        #pragma unroll
        for (int j = 0; j < 4; j++) {
            bb[j]     = bm1[jt * 192 + c0 + j];
            bb[4 + j] = bm1[jt * 192 + c0 + 96 + j];
        }
        #pragma unroll
        for (int i = 0; i < 4; i++) {
            float g[8];
            #pragma unroll
            for (int j = 0; j < 8; j++) {
                const float v = acc1[i][j] + bb[j];
                g[j] = 0.5f * v * (1.f + erff(v * 0.70710678118654752f));
            }
            *(float4*)&sm[OFF_V + (r0 + i) * 192 + c0]      = *(float4*)&g[0];
            *(float4*)&sm[OFF_V + (r0 + i) * 192 + c0 + 96] = *(float4*)&g[4];
        }
        gemm_full<1>(sm, &sm[OFF_V], wm2 + (size_t)jt * 192 * 192, 192, 0, tid, r0, c0, acc2);
    }

    // ---- residual + staged scatter (3 chunks of 64 cols via P, stride 65) ----
    {
        float bb[8];
        #pragma unroll
        for (int j = 0; j < 4; j++) { bb[j] = bm2[c0 + j]; bb[4 + j] = bm2[c0 + 96 + j]; }
        for (int ch = 0; ch < 3; ch++) {
            __syncthreads();
            #pragma unroll
            for (int g = 0; g < 2; g++) {
                const int cb = c0 + 96 * g;
                if ((cb >> 6) == ch) {
                    #pragma unroll
                    for (int j = 0; j < 4; j++)
                        #pragma unroll
                        for (int i = 0; i < 4; i++) {
                            const float v = acc2[i][4 * g + j] + bb[4 * g + j]
                                          + sm[OFF_X + (cb + j) * XS + r0 + i];
                            sm[OFF_P + ((cb + j) & 63) * PS + r0 + i] = v;
                        }
                }
            }
            __syncthreads();
            for (int l = tid; l < 1024; l += 384) {
                const int cl  = l >> 4;
                const int r16 = l & 15;
                const int ty  = r16 >> 1, half = r16 & 1;
                const int c   = ch * 64 + cl;
                const int sh  = (hb * 8 + ty + 4) & 255;
                const int sw  = (wb * 8 + half * 4 + 4) & 255;
                const int base = OFF_P + cl * PS + ty * 8 + half * 4;
                float4 v;
                v.x = sm[base]; v.y = sm[base + 1]; v.z = sm[base + 2]; v.w = sm[base + 3];
                *(float4*)&out[(((size_t)(b * 192 + c)) << 16) + (sh << 8) + sw] = v;
            }
        }
    }
}

extern "C" void kernel_launch(void* const* d_in, const int* in_sizes, int n_in,
                              void* d_out, int out_size)
{
    (void)in_sizes; (void)n_in; (void)out_size;
    const float* x    = (const float*)d_in[0];
    const float* g1   = (const float*)d_in[1];
    const float* b1   = (const float*)d_in[2];
    const float* wqkv = (const float*)d_in[3];
    const float* bqkv = (const float*)d_in[4];
    const float* wo   = (const float*)d_in[5];
    const float* bo   = (const float*)d_in[6];
    const float* g2   = (const float*)d_in[7];
    const float* b2   = (const float*)d_in[8];
    const float* wm1  = (const float*)d_in[9];
    const float* bm1  = (const float*)d_in[10];
    const float* wm2  = (const float*)d_in[11];
    const float* bm2  = (const float*)d_in[12];
    float* out = (float*)d_out;

    cudaFuncSetAttribute(swin_block_kernel,
                         cudaFuncAttributeMaxDynamicSharedMemorySize, SMEM_BYTES);
    swin_block_kernel<<<4096, 384, SMEM_BYTES>>>(
        x, g1, b1, wqkv, bqkv, wo, bo, g2, b2, wm1, bm1, wm2, bm2, out);
}

// round 6
// speedup vs baseline: 8.0990x; 1.9268x over previous
#include <cuda_runtime.h>
#include <math.h>
#include <stdint.h>

// x: (4,192,256,256) fp32, WS=8, shift=4, NHEADS=4, HD=48, nW=4096, T=64
// 384 threads (12 warps), 1 window/CTA. tf32 mma.sync m16n8k8 everywhere.
// Activation buffers t-major stride 196 (=4 mod 32): A-frag AND transposed
// B-frag loads are bank-conflict-free. Weight stage stride 200 (=8 mod 32).
#define SA 196
#define SP 68
#define SW 200
#define OFF_X 0          // LN1 out / residual  64x196 = 12544 f
#define OFF_Q 12544      // Q -> O concat
#define OFF_K 25088      // K -> H (LN2 out)
#define OFF_V 37632      // V -> G (gelu out)
#define OFF_P 50176      // scores 64x68 / LN scratch / out staging = 4352 f
#define OFF_W 54528      // weight stage 16x200 = 3200 f
#define SMEM_FLOATS 57728
#define SMEM_BYTES (SMEM_FLOATS * 4)   // 230912 B

__device__ __forceinline__ void mma_tf32(float (&d)[4],
                                         uint32_t a0, uint32_t a1, uint32_t a2, uint32_t a3,
                                         uint32_t b0, uint32_t b1)
{
    asm volatile(
        "mma.sync.aligned.m16n8k8.row.col.f32.tf32.tf32.f32 "
        "{%0,%1,%2,%3}, {%4,%5,%6,%7}, {%8,%9}, {%0,%1,%2,%3};"
        : "+f"(d[0]), "+f"(d[1]), "+f"(d[2]), "+f"(d[3])
        : "r"(a0), "r"(a1), "r"(a2), "r"(a3), "r"(b0), "r"(b1));
}

// acc[8][4] += A(64x192, t-major SA) @ w[:, col0+0..191]; warp tile m16 x n64
__device__ __forceinline__ void gemm_mma(float* __restrict__ sm,
                                         const float* __restrict__ sA,
                                         const float* __restrict__ w,
                                         int wld, int col0,
                                         int tid, int mi, int n0,
                                         float (&acc)[8][4])
{
    const int lane = tid & 31, gr = lane >> 2, tg = lane & 3;
    for (int k0 = 0; k0 < 192; k0 += 16) {
        #pragma unroll
        for (int it = 0; it < 2; it++) {
            const int l = tid + it * 384;          // 0..767 float4 (16 x 48)
            const int kk = l / 48, j4 = l - kk * 48;
            *(float4*)&sm[OFF_W + kk * SW + j4 * 4] =
                *(const float4*)&w[(size_t)(k0 + kk) * wld + col0 + j4 * 4];
        }
        __syncthreads();
        #pragma unroll
        for (int ks = 0; ks < 2; ks++) {
            const float* Ab = sA + (mi * 16 + gr) * SA + k0 + ks * 8 + tg;
            const uint32_t a0 = __float_as_uint(Ab[0]);
            const uint32_t a1 = __float_as_uint(Ab[8 * SA]);
            const uint32_t a2 = __float_as_uint(Ab[4]);
            const uint32_t a3 = __float_as_uint(Ab[8 * SA + 4]);
            const float* Bb = &sm[OFF_W + (ks * 8 + tg) * SW + n0 + gr];
            #pragma unroll
            for (int j = 0; j < 8; j++) {
                const uint32_t b0 = __float_as_uint(Bb[j * 8]);
                const uint32_t b1 = __float_as_uint(Bb[4 * SW + j * 8]);
                mma_tf32(acc[j], a0, a1, a2, a3, b0, b1);
            }
        }
        __syncthreads();
    }
}

// token-parallel LayerNorm on t-major buffers (sync at entry and exit)
__device__ __forceinline__ void layernorm(float* __restrict__ sm,
                                          int src, int dst,
                                          const float* __restrict__ g,
                                          const float* __restrict__ bp,
                                          int tid)
{
    __syncthreads();
    const int t = tid & 63, chk = tid >> 6;       // 6 chunks of 32 channels
    {
        const float* row = &sm[src + t * SA + chk * 32];
        float s = 0.f, s2 = 0.f;
        #pragma unroll
        for (int j4 = 0; j4 < 8; j4++) {
            const float4 v = *(const float4*)&row[j4 * 4];
            s  += v.x + v.y + v.z + v.w;
            s2 += v.x * v.x + v.y * v.y + v.z * v.z + v.w * v.w;
        }
        sm[OFF_P + chk * 64 + t]       = s;
        sm[OFF_P + 384 + chk * 64 + t] = s2;
    }
    __syncthreads();
    if (tid < 64) {
        float s = 0.f, s2 = 0.f;
        #pragma unroll
        for (int ch = 0; ch < 6; ch++) {
            s  += sm[OFF_P + ch * 64 + tid];
            s2 += sm[OFF_P + 384 + ch * 64 + tid];
        }
        const float mean = s * (1.f / 192.f);
        const float var  = s2 * (1.f / 192.f) - mean * mean;
        sm[OFF_P + 768 + tid] = mean;
        sm[OFF_P + 832 + tid] = rsqrtf(var + 1e-5f);
    }
    __syncthreads();
    {
        const float mean = sm[OFF_P + 768 + t];
        const float rstd = sm[OFF_P + 832 + t];
        const float* row = &sm[src + t * SA + chk * 32];
        float* drow = &sm[dst + t * SA + chk * 32];
        #pragma unroll
        for (int j4 = 0; j4 < 8; j4++) {
            float4 v = *(const float4*)&row[j4 * 4];
            const float4 gg = *(const float4*)&g[chk * 32 + j4 * 4];
            const float4 bb = *(const float4*)&bp[chk * 32 + j4 * 4];
            v.x = (v.x - mean) * rstd * gg.x + bb.x;
            v.y = (v.y - mean) * rstd * gg.y + bb.y;
            v.z = (v.z - mean) * rstd * gg.z + bb.z;
            v.w = (v.w - mean) * rstd * gg.w + bb.w;
            *(float4*)&drow[j4 * 4] = v;
        }
    }
    __syncthreads();
}

__global__ __launch_bounds__(384, 1)
void swin_block_kernel(const float* __restrict__ x,
                       const float* __restrict__ g1,  const float* __restrict__ b1,
                       const float* __restrict__ wqkv,const float* __restrict__ bqkv,
                       const float* __restrict__ wo,  const float* __restrict__ bo,
                       const float* __restrict__ g2,  const float* __restrict__ b2,
                       const float* __restrict__ wm1, const float* __restrict__ bm1,
                       const float* __restrict__ wm2, const float* __restrict__ bm2,
                       float* __restrict__ out)
{
    extern __shared__ float sm[];
    const int tid  = threadIdx.x;
    const int wid  = tid >> 5;
    const int lane = tid & 31;
    const int gr   = lane >> 2, tg = lane & 3;
    const int mi   = wid & 3;               // m-tile (16 rows)
    const int ns   = wid >> 2;              // n-slab (64 cols)
    const int n0   = ns * 64;
    const int wi   = blockIdx.x;
    const int b    = wi >> 10;
    const int hb   = (wi >> 5) & 31;
    const int wb   = wi & 31;

    // ---- gather window into X (t-major), shift folded, coalesced gmem float4 ----
    for (int l = tid; l < 3072; l += 384) {
        const int c    = l >> 4;
        const int r16  = l & 15;
        const int ty   = r16 >> 1, half = r16 & 1;
        const int sh   = (hb * 8 + ty + 4) & 255;
        const int sw   = (wb * 8 + half * 4 + 4) & 255;
        const float4 v = *(const float4*)&x[(((size_t)(b * 192 + c)) << 16) + (sh << 8) + sw];
        const int t0 = ty * 8 + half * 4;
        sm[OFF_X + (t0 + 0) * SA + c] = v.x;
        sm[OFF_X + (t0 + 1) * SA + c] = v.y;
        sm[OFF_X + (t0 + 2) * SA + c] = v.z;
        sm[OFF_X + (t0 + 3) * SA + c] = v.w;
    }

    // ---- LN1 in place (residual base = LN1 output) ----
    layernorm(sm, OFF_X, OFF_X, g1, b1, tid);

    // ---- q / k / v GEMMs (tf32 mma) ----
    #pragma unroll 1
    for (int p = 0; p < 3; p++) {
        float acc[8][4];
        #pragma unroll
        for (int j = 0; j < 8; j++)
            #pragma unroll
            for (int r = 0; r < 4; r++) acc[j][r] = 0.f;
        gemm_mma(sm, &sm[OFF_X], wqkv, 576, p * 192, tid, mi, n0, acc);
        float* dst = &sm[(p == 0) ? OFF_Q : (p == 1) ? OFF_K : OFF_V];
        const int row = mi * 16 + gr;
        #pragma unroll
        for (int j = 0; j < 8; j++) {
            const int col = n0 + j * 8 + 2 * tg;
            const float bb0 = __ldg(&bqkv[p * 192 + col]);
            const float bb1 = __ldg(&bqkv[p * 192 + col + 1]);
            dst[row * SA + col]           = acc[j][0] + bb0;
            dst[row * SA + col + 1]       = acc[j][1] + bb1;
            dst[(row + 8) * SA + col]     = acc[j][2] + bb0;
            dst[(row + 8) * SA + col + 1] = acc[j][3] + bb1;
        }
    }
    __syncthreads();

    // ---- attention per head (tf32 mma); O written into Q slab in place ----
    const float scale = 0.14433756729740643f;     // 1/sqrt(48)
    for (int h = 0; h < 4; h++) {
        // scores: S = Q_h @ K_h^T  (B-frag = transposed read of t-major K)
        for (int t = wid; t < 32; t += 12) {
            const int mi2 = t >> 3, ni = t & 7;
            float sc[4] = {0.f, 0.f, 0.f, 0.f};
            const float* Ab = &sm[OFF_Q + (mi2 * 16 + gr) * SA + h * 48 + tg];
            const float* Bb = &sm[OFF_K + (ni * 8 + gr) * SA + h * 48 + tg];
            #pragma unroll
            for (int k8 = 0; k8 < 6; k8++) {
                const uint32_t a0 = __float_as_uint(Ab[k8 * 8]);
                const uint32_t a1 = __float_as_uint(Ab[8 * SA + k8 * 8]);
                const uint32_t a2 = __float_as_uint(Ab[k8 * 8 + 4]);
                const uint32_t a3 = __float_as_uint(Ab[8 * SA + k8 * 8 + 4]);
                const uint32_t b0 = __float_as_uint(Bb[k8 * 8]);
                const uint32_t b1 = __float_as_uint(Bb[k8 * 8 + 4]);
                mma_tf32(sc, a0, a1, a2, a3, b0, b1);
            }
            const int row = mi2 * 16 + gr, col = ni * 8 + 2 * tg;
            sm[OFF_P + row * SP + col]           = sc[0] * scale;
            sm[OFF_P + row * SP + col + 1]       = sc[1] * scale;
            sm[OFF_P + (row + 8) * SP + col]     = sc[2] * scale;
            sm[OFF_P + (row + 8) * SP + col + 1] = sc[3] * scale;
        }
        __syncthreads();

        if (tid < 256) {          // softmax over 64 keys (4 threads/row), fp32 exact
            const int t = tid >> 2, qd = tid & 3;
            float* pr = &sm[OFF_P + t * SP + qd * 16];
            float m = -1e30f;
            #pragma unroll
            for (int j = 0; j < 16; j++) m = fmaxf(m, pr[j]);
            m = fmaxf(m, __shfl_xor_sync(0xffffffffu, m, 1));
            m = fmaxf(m, __shfl_xor_sync(0xffffffffu, m, 2));
            float s = 0.f;
            #pragma unroll
            for (int j = 0; j < 16; j++) { const float e = __expf(pr[j] - m); pr[j] = e; s += e; }
            s += __shfl_xor_sync(0xffffffffu, s, 1);
            s += __shfl_xor_sync(0xffffffffu, s, 2);
            const float inv = 1.f / s;
            #pragma unroll
            for (int j = 0; j < 16; j++) pr[j] *= inv;
        }
        __syncthreads();

        // AV: O_h = P @ V_h  (A = P stride 68 (=4 mod 32), B-frag = transposed V)
        for (int t = wid; t < 24; t += 12) {
            const int mi2 = t / 6, ci = t % 6;
            float ao[4] = {0.f, 0.f, 0.f, 0.f};
            const float* Ab = &sm[OFF_P + (mi2 * 16 + gr) * SP + tg];
            const float* Bb = &sm[OFF_V + tg * SA + h * 48 + ci * 8 + gr];
            #pragma unroll
            for (int k8 = 0; k8 < 8; k8++) {
                const uint32_t a0 = __float_as_uint(Ab[k8 * 8]);
                const uint32_t a1 = __float_as_uint(Ab[8 * SP + k8 * 8]);
                const uint32_t a2 = __float_as_uint(Ab[k8 * 8 + 4]);
                const uint32_t a3 = __float_as_uint(Ab[8 * SP + k8 * 8 + 4]);
                const uint32_t b0 = __float_as_uint(Bb[k8 * 8 * SA]);
                const uint32_t b1 = __float_as_uint(Bb[(k8 * 8 + 4) * SA]);
                mma_tf32(ao, a0, a1, a2, a3, b0, b1);
            }
            const int row = mi2 * 16 + gr, col = h * 48 + ci * 8 + 2 * tg;
            sm[OFF_Q + row * SA + col]           = ao[0];
            sm[OFF_Q + row * SA + col + 1]       = ao[1];
            sm[OFF_Q + (row + 8) * SA + col]     = ao[2];
            sm[OFF_Q + (row + 8) * SA + col + 1] = ao[3];
        }
        __syncthreads();
    }

    // ---- o-proj + residual RMW into X ----
    {
        float acc[8][4];
        #pragma unroll
        for (int j = 0; j < 8; j++)
            #pragma unroll
            for (int r = 0; r < 4; r++) acc[j][r] = 0.f;
        gemm_mma(sm, &sm[OFF_Q], wo, 192, 0, tid, mi, n0, acc);
        const int row = mi * 16 + gr;
        #pragma unroll
        for (int j = 0; j < 8; j++) {
            const int col = n0 + j * 8 + 2 * tg;
            const float bb0 = __ldg(&bo[col]);
            const float bb1 = __ldg(&bo[col + 1]);
            sm[OFF_X + row * SA + col]           += acc[j][0] + bb0;
            sm[OFF_X + row * SA + col + 1]       += acc[j][1] + bb1;
            sm[OFF_X + (row + 8) * SA + col]     += acc[j][2] + bb0;
            sm[OFF_X + (row + 8) * SA + col + 1] += acc[j][3] + bb1;
        }
    }

    // ---- LN2: X -> H (K slab) ----
    layernorm(sm, OFF_X, OFF_K, g2, b2, tid);

    // ---- MLP: 4 hidden slabs of 192; G reuses V slab ----
    float acc2[8][4];
    #pragma unroll
    for (int j = 0; j < 8; j++)
        #pragma unroll
        for (int r = 0; r < 4; r++) acc2[j][r] = 0.f;

    #pragma unroll 1
    for (int jt = 0; jt < 4; jt++) {
        float acc1[8][4];
        #pragma unroll
        for (int j = 0; j < 8; j++)
            #pragma unroll
            for (int r = 0; r < 4; r++) acc1[j][r] = 0.f;
        gemm_mma(sm, &sm[OFF_K], wm1, 768, jt * 192, tid, mi, n0, acc1);
        const int row = mi * 16 + gr;
        #pragma unroll
        for (int j = 0; j < 8; j++) {
            const int col = n0 + j * 8 + 2 * tg;
            const float bb0 = __ldg(&bm1[jt * 192 + col]);
            const float bb1 = __ldg(&bm1[jt * 192 + col + 1]);
            float v0 = acc1[j][0] + bb0, v1 = acc1[j][1] + bb1;
            float v2 = acc1[j][2] + bb0, v3 = acc1[j][3] + bb1;
            v0 = 0.5f * v0 * (1.f + erff(v0 * 0.70710678118654752f));
            v1 = 0.5f * v1 * (1.f + erff(v1 * 0.70710678118654752f));
            v2 = 0.5f * v2 * (1.f + erff(v2 * 0.70710678118654752f));
            v3 = 0.5f * v3 * (1.f + erff(v3 * 0.70710678118654752f));
            sm[OFF_V + row * SA + col]           = v0;
            sm[OFF_V + row * SA + col + 1]       = v1;
            sm[OFF_V + (row + 8) * SA + col]     = v2;
            sm[OFF_V + (row + 8) * SA + col + 1] = v3;
        }
        // first barrier inside gemm_mma orders the G writes
        gemm_mma(sm, &sm[OFF_V], wm2 + (size_t)jt * 192 * 192, 192, 0, tid, mi, n0, acc2);
    }

    // ---- residual + staged scatter (3 chunks of 64 cols via P) ----
    {
        const int row = mi * 16 + gr;
        for (int ch = 0; ch < 3; ch++) {
            __syncthreads();
            if (ns == ch) {
                #pragma unroll
                for (int j = 0; j < 8; j++) {
                    const int col = n0 + j * 8 + 2 * tg;
                    const int cl  = col & 63;
                    const float bb0 = __ldg(&bm2[col]);
                    const float bb1 = __ldg(&bm2[col + 1]);
                    sm[OFF_P + cl * SP + row]           = acc2[j][0] + bb0 + sm[OFF_X + row * SA + col];
                    sm[OFF_P + (cl + 1) * SP + row]     = acc2[j][1] + bb1 + sm[OFF_X + row * SA + col + 1];
                    sm[OFF_P + cl * SP + row + 8]       = acc2[j][2] + bb0 + sm[OFF_X + (row + 8) * SA + col];
                    sm[OFF_P + (cl + 1) * SP + row + 8] = acc2[j][3] + bb1 + sm[OFF_X + (row + 8) * SA + col + 1];
                }
            }
            __syncthreads();
            for (int l = tid; l < 1024; l += 384) {
                const int cl  = l >> 4;
                const int r16 = l & 15;
                const int ty  = r16 >> 1, half = r16 & 1;
                const int c   = ch * 64 + cl;
                const int sh  = (hb * 8 + ty + 4) & 255;
                const int sw  = (wb * 8 + half * 4 + 4) & 255;
                const float4 v = *(const float4*)&sm[OFF_P + cl * SP + ty * 8 + half * 4];
                *(float4*)&out[(((size_t)(b * 192 + c)) << 16) + (sh << 8) + sw] = v;
            }
        }
    }
}

extern "C" void kernel_launch(void* const* d_in, const int* in_sizes, int n_in,
                              void* d_out, int out_size)
{
    (void)in_sizes; (void)n_in; (void)out_size;
    const float* x    = (const float*)d_in[0];
    const float* g1   = (const float*)d_in[1];
    const float* b1   = (const float*)d_in[2];
    const float* wqkv = (const float*)d_in[3];
    const float* bqkv = (const float*)d_in[4];
    const float* wo   = (const float*)d_in[5];
    const float* bo   = (const float*)d_in[6];
    const float* g2   = (const float*)d_in[7];
    const float* b2   = (const float*)d_in[8];
    const float* wm1  = (const float*)d_in[9];
    const float* bm1  = (const float*)d_in[10];
    const float* wm2  = (const float*)d_in[11];
    const float* bm2  = (const float*)d_in[12];
    float* out = (float*)d_out;

    cudaFuncSetAttribute(swin_block_kernel,
                         cudaFuncAttributeMaxDynamicSharedMemorySize, SMEM_BYTES);
    swin_block_kernel<<<4096, 384, SMEM_BYTES>>>(
        x, g1, b1, wqkv, bqkv, wo, bo, g2, b2, wm1, bm1, wm2, bm2, out);
}

// round 7
// speedup vs baseline: 9.6505x; 1.1916x over previous
#include <cuda_runtime.h>
#include <math.h>
#include <stdint.h>

// x: (4,192,256,256) fp32, WS=8, shift=4, NHEADS=4, HD=48, nW=4096, T=64
// 384 threads (12 warps), 1 window/CTA. tf32 mma.sync m16n8k8.
// B-fragments read DIRECTLY from global (L2-resident weights) -> no weight
// staging, no GEMM-internal barriers. Warp tile m32 x n32 (2m x 6n).
// Activation buffers t-major stride 196 (=4 mod 32): conflict-free frags.
#define SA 196
#define SP 68
#define OFF_X 0          // LN1 out / residual  64x196 = 12544 f
#define OFF_Q 12544      // Q -> O concat
#define OFF_K 25088      // K -> H (LN2 out)
#define OFF_V 37632      // V -> G (gelu out)
#define OFF_P 50176      // scores 64x68 / LN scratch / out staging = 4352 f
#define SMEM_FLOATS 54528
#define SMEM_BYTES (SMEM_FLOATS * 4)   // 218112 B

__device__ __forceinline__ void mma_tf32(float (&d)[4],
                                         uint32_t a0, uint32_t a1, uint32_t a2, uint32_t a3,
                                         uint32_t b0, uint32_t b1)
{
    asm volatile(
        "mma.sync.aligned.m16n8k8.row.col.f32.tf32.tf32.f32 "
        "{%0,%1,%2,%3}, {%4,%5,%6,%7}, {%8,%9}, {%0,%1,%2,%3};"
        : "+f"(d[0]), "+f"(d[1]), "+f"(d[2]), "+f"(d[3])
        : "r"(a0), "r"(a1), "r"(a2), "r"(a3), "r"(b0), "r"(b1));
}

// acc[2][4][4] += A(64x192 smem, t-major SA) @ w[:, col0 + nj*32 .. +32]
// warp tile: rows mi*32..+32, cols nj*32..+32. NO barriers inside.
__device__ __forceinline__ void gemm_direct(const float* __restrict__ sA,
                                            const float* __restrict__ w,
                                            int wld, int col0,
                                            int lane, int mi, int nj,
                                            float (&acc)[2][4][4])
{
    const int gr = lane >> 2, tg = lane & 3;
    const float* A0 = sA + (mi * 32 + gr) * SA + tg;
    const float* W0 = w + (size_t)tg * wld + col0 + nj * 32 + gr;
    #pragma unroll 4
    for (int k8 = 0; k8 < 24; k8++) {
        uint32_t b0[4], b1[4];
        const float* Bb = W0 + (size_t)(k8 * 8) * wld;
        #pragma unroll
        for (int sn = 0; sn < 4; sn++) {
            b0[sn] = __float_as_uint(__ldg(&Bb[sn * 8]));
            b1[sn] = __float_as_uint(__ldg(&Bb[4 * wld + sn * 8]));
        }
        #pragma unroll
        for (int sm_i = 0; sm_i < 2; sm_i++) {
            const float* Ab = A0 + sm_i * 16 * SA + k8 * 8;
            const uint32_t a0 = __float_as_uint(Ab[0]);
            const uint32_t a1 = __float_as_uint(Ab[8 * SA]);
            const uint32_t a2 = __float_as_uint(Ab[4]);
            const uint32_t a3 = __float_as_uint(Ab[8 * SA + 4]);
            #pragma unroll
            for (int sn = 0; sn < 4; sn++)
                mma_tf32(acc[sm_i][sn], a0, a1, a2, a3, b0[sn], b1[sn]);
        }
    }
}

// token-parallel LayerNorm on t-major buffers (sync at entry and exit)
__device__ __forceinline__ void layernorm(float* __restrict__ sm,
                                          int src, int dst,
                                          const float* __restrict__ g,
                                          const float* __restrict__ bp,
                                          int tid)
{
    __syncthreads();
    const int t = tid & 63, chk = tid >> 6;       // 6 chunks of 32 channels
    {
        const float* row = &sm[src + t * SA + chk * 32];
        float s = 0.f, s2 = 0.f;
        #pragma unroll
        for (int j4 = 0; j4 < 8; j4++) {
            const float4 v = *(const float4*)&row[j4 * 4];
            s  += v.x + v.y + v.z + v.w;
            s2 += v.x * v.x + v.y * v.y + v.z * v.z + v.w * v.w;
        }
        sm[OFF_P + chk * 64 + t]       = s;
        sm[OFF_P + 384 + chk * 64 + t] = s2;
    }
    __syncthreads();
    if (tid < 64) {
        float s = 0.f, s2 = 0.f;
        #pragma unroll
        for (int ch = 0; ch < 6; ch++) {
            s  += sm[OFF_P + ch * 64 + tid];
            s2 += sm[OFF_P + 384 + ch * 64 + tid];
        }
        const float mean = s * (1.f / 192.f);
        const float var  = s2 * (1.f / 192.f) - mean * mean;
        sm[OFF_P + 768 + tid] = mean;
        sm[OFF_P + 832 + tid] = rsqrtf(var + 1e-5f);
    }
    __syncthreads();
    {
        const float mean = sm[OFF_P + 768 + t];
        const float rstd = sm[OFF_P + 832 + t];
        const float* row = &sm[src + t * SA + chk * 32];
        float* drow = &sm[dst + t * SA + chk * 32];
        #pragma unroll
        for (int j4 = 0; j4 < 8; j4++) {
            float4 v = *(const float4*)&row[j4 * 4];
            const float4 gg = *(const float4*)&g[chk * 32 + j4 * 4];
            const float4 bb = *(const float4*)&bp[chk * 32 + j4 * 4];
            v.x = (v.x - mean) * rstd * gg.x + bb.x;
            v.y = (v.y - mean) * rstd * gg.y + bb.y;
            v.z = (v.z - mean) * rstd * gg.z + bb.z;
            v.w = (v.w - mean) * rstd * gg.w + bb.w;
            *(float4*)&drow[j4 * 4] = v;
        }
    }
    __syncthreads();
}

__global__ __launch_bounds__(384, 1)
void swin_block_kernel(const float* __restrict__ x,
                       const float* __restrict__ g1,  const float* __restrict__ b1,
                       const float* __restrict__ wqkv,const float* __restrict__ bqkv,
                       const float* __restrict__ wo,  const float* __restrict__ bo,
                       const float* __restrict__ g2,  const float* __restrict__ b2,
                       const float* __restrict__ wm1, const float* __restrict__ bm1,
                       const float* __restrict__ wm2, const float* __restrict__ bm2,
                       float* __restrict__ out)
{
    extern __shared__ float sm[];
    const int tid  = threadIdx.x;
    const int wid  = tid >> 5;
    const int lane = tid & 31;
    const int gr   = lane >> 2, tg = lane & 3;
    const int mi   = wid & 1;               // 2 m-tiles of 32 rows
    const int nj   = wid >> 1;              // 6 n-tiles of 32 cols
    const int wi   = blockIdx.x;
    const int b    = wi >> 10;
    const int hb   = (wi >> 5) & 31;
    const int wb   = wi & 31;

    // ---- gather window into X (t-major), shift folded, coalesced gmem float4 ----
    for (int l = tid; l < 3072; l += 384) {
        const int c    = l >> 4;
        const int r16  = l & 15;
        const int ty   = r16 >> 1, half = r16 & 1;
        const int sh   = (hb * 8 + ty + 4) & 255;
        const int sw   = (wb * 8 + half * 4 + 4) & 255;
        const float4 v = *(const float4*)&x[(((size_t)(b * 192 + c)) << 16) + (sh << 8) + sw];
        const int t0 = ty * 8 + half * 4;
        sm[OFF_X + (t0 + 0) * SA + c] = v.x;
        sm[OFF_X + (t0 + 1) * SA + c] = v.y;
        sm[OFF_X + (t0 + 2) * SA + c] = v.z;
        sm[OFF_X + (t0 + 3) * SA + c] = v.w;
    }

    // ---- LN1 in place (residual base = LN1 output) ----
    layernorm(sm, OFF_X, OFF_X, g1, b1, tid);

    // ---- q / k / v GEMMs (no barriers inside; distinct output tiles) ----
    #pragma unroll 1
    for (int p = 0; p < 3; p++) {
        float acc[2][4][4];
        #pragma unroll
        for (int s = 0; s < 2; s++)
            #pragma unroll
            for (int n = 0; n < 4; n++)
                #pragma unroll
                for (int r = 0; r < 4; r++) acc[s][n][r] = 0.f;
        gemm_direct(&sm[OFF_X], wqkv, 576, p * 192, lane, mi, nj, acc);
        float* dst = &sm[(p == 0) ? OFF_Q : (p == 1) ? OFF_K : OFF_V];
        #pragma unroll
        for (int s = 0; s < 2; s++) {
            const int row = mi * 32 + s * 16 + gr;
            #pragma unroll
            for (int n = 0; n < 4; n++) {
                const int col = nj * 32 + n * 8 + 2 * tg;
                const float bb0 = __ldg(&bqkv[p * 192 + col]);
                const float bb1 = __ldg(&bqkv[p * 192 + col + 1]);
                dst[row * SA + col]           = acc[s][n][0] + bb0;
                dst[row * SA + col + 1]       = acc[s][n][1] + bb1;
                dst[(row + 8) * SA + col]     = acc[s][n][2] + bb0;
                dst[(row + 8) * SA + col + 1] = acc[s][n][3] + bb1;
            }
        }
    }
    __syncthreads();

    // ---- attention per head (tf32 mma); O written into Q slab in place ----
    const float scale = 0.14433756729740643f;     // 1/sqrt(48)
    for (int h = 0; h < 4; h++) {
        // scores: S = Q_h @ K_h^T  (B-frag = transposed read of t-major K)
        for (int t = wid; t < 32; t += 12) {
            const int mi2 = t >> 3, ni = t & 7;
            float sc[4] = {0.f, 0.f, 0.f, 0.f};
            const float* Ab = &sm[OFF_Q + (mi2 * 16 + gr) * SA + h * 48 + tg];
            const float* Bb = &sm[OFF_K + (ni * 8 + gr) * SA + h * 48 + tg];
            #pragma unroll
            for (int k8 = 0; k8 < 6; k8++) {
                const uint32_t a0 = __float_as_uint(Ab[k8 * 8]);
                const uint32_t a1 = __float_as_uint(Ab[8 * SA + k8 * 8]);
                const uint32_t a2 = __float_as_uint(Ab[k8 * 8 + 4]);
                const uint32_t a3 = __float_as_uint(Ab[8 * SA + k8 * 8 + 4]);
                const uint32_t b0 = __float_as_uint(Bb[k8 * 8]);
                const uint32_t b1 = __float_as_uint(Bb[k8 * 8 + 4]);
                mma_tf32(sc, a0, a1, a2, a3, b0, b1);
            }
            const int row = mi2 * 16 + gr, col = ni * 8 + 2 * tg;
            sm[OFF_P + row * SP + col]           = sc[0] * scale;
            sm[OFF_P + row * SP + col + 1]       = sc[1] * scale;
            sm[OFF_P + (row + 8) * SP + col]     = sc[2] * scale;
            sm[OFF_P + (row + 8) * SP + col + 1] = sc[3] * scale;
        }
        __syncthreads();

        if (tid < 256) {          // softmax over 64 keys (4 threads/row), fp32 exact
            const int t = tid >> 2, qd = tid & 3;
            float* pr = &sm[OFF_P + t * SP + qd * 16];
            float m = -1e30f;
            #pragma unroll
            for (int j = 0; j < 16; j++) m = fmaxf(m, pr[j]);
            m = fmaxf(m, __shfl_xor_sync(0xffffffffu, m, 1));
            m = fmaxf(m, __shfl_xor_sync(0xffffffffu, m, 2));
            float s = 0.f;
            #pragma unroll
            for (int j = 0; j < 16; j++) { const float e = __expf(pr[j] - m); pr[j] = e; s += e; }
            s += __shfl_xor_sync(0xffffffffu, s, 1);
            s += __shfl_xor_sync(0xffffffffu, s, 2);
            const float inv = 1.f / s;
            #pragma unroll
            for (int j = 0; j < 16; j++) pr[j] *= inv;
        }
        __syncthreads();

        // AV: O_h = P @ V_h  (A = P stride 68, B-frag = transposed V)
        for (int t = wid; t < 24; t += 12) {
            const int mi2 = t / 6, ci = t % 6;
            float ao[4] = {0.f, 0.f, 0.f, 0.f};
            const float* Ab = &sm[OFF_P + (mi2 * 16 + gr) * SP + tg];
            const float* Bb = &sm[OFF_V + tg * SA + h * 48 + ci * 8 + gr];
            #pragma unroll
            for (int k8 = 0; k8 < 8; k8++) {
                const uint32_t a0 = __float_as_uint(Ab[k8 * 8]);
                const uint32_t a1 = __float_as_uint(Ab[8 * SP + k8 * 8]);
                const uint32_t a2 = __float_as_uint(Ab[k8 * 8 + 4]);
                const uint32_t a3 = __float_as_uint(Ab[8 * SP + k8 * 8 + 4]);
                const uint32_t b0 = __float_as_uint(Bb[k8 * 8 * SA]);
                const uint32_t b1 = __float_as_uint(Bb[(k8 * 8 + 4) * SA]);
                mma_tf32(ao, a0, a1, a2, a3, b0, b1);
            }
            const int row = mi2 * 16 + gr, col = h * 48 + ci * 8 + 2 * tg;
            sm[OFF_Q + row * SA + col]           = ao[0];
            sm[OFF_Q + row * SA + col + 1]       = ao[1];
            sm[OFF_Q + (row + 8) * SA + col]     = ao[2];
            sm[OFF_Q + (row + 8) * SA + col + 1] = ao[3];
        }
        __syncthreads();
    }

    // ---- o-proj + residual RMW into X ----
    {
        float acc[2][4][4];
        #pragma unroll
        for (int s = 0; s < 2; s++)
            #pragma unroll
            for (int n = 0; n < 4; n++)
                #pragma unroll
                for (int r = 0; r < 4; r++) acc[s][n][r] = 0.f;
        gemm_direct(&sm[OFF_Q], wo, 192, 0, lane, mi, nj, acc);
        #pragma unroll
        for (int s = 0; s < 2; s++) {
            const int row = mi * 32 + s * 16 + gr;
            #pragma unroll
            for (int n = 0; n < 4; n++) {
                const int col = nj * 32 + n * 8 + 2 * tg;
                const float bb0 = __ldg(&bo[col]);
                const float bb1 = __ldg(&bo[col + 1]);
                sm[OFF_X + row * SA + col]           += acc[s][n][0] + bb0;
                sm[OFF_X + row * SA + col + 1]       += acc[s][n][1] + bb1;
                sm[OFF_X + (row + 8) * SA + col]     += acc[s][n][2] + bb0;
                sm[OFF_X + (row + 8) * SA + col + 1] += acc[s][n][3] + bb1;
            }
        }
    }

    // ---- LN2: X -> H (K slab) ----
    layernorm(sm, OFF_X, OFF_K, g2, b2, tid);

    // ---- MLP: 4 hidden slabs of 192; G reuses V slab ----
    float acc2[2][4][4];
    #pragma unroll
    for (int s = 0; s < 2; s++)
        #pragma unroll
        for (int n = 0; n < 4; n++)
            #pragma unroll
            for (int r = 0; r < 4; r++) acc2[s][n][r] = 0.f;

    #pragma unroll 1
    for (int jt = 0; jt < 4; jt++) {
        float acc1[2][4][4];
        #pragma unroll
        for (int s = 0; s < 2; s++)
            #pragma unroll
            for (int n = 0; n < 4; n++)
                #pragma unroll
                for (int r = 0; r < 4; r++) acc1[s][n][r] = 0.f;
        gemm_direct(&sm[OFF_K], wm1, 768, jt * 192, lane, mi, nj, acc1);
        #pragma unroll
        for (int s = 0; s < 2; s++) {
            const int row = mi * 32 + s * 16 + gr;
            #pragma unroll
            for (int n = 0; n < 4; n++) {
                const int col = nj * 32 + n * 8 + 2 * tg;
                const float bb0 = __ldg(&bm1[jt * 192 + col]);
                const float bb1 = __ldg(&bm1[jt * 192 + col + 1]);
                float v0 = acc1[s][n][0] + bb0, v1 = acc1[s][n][1] + bb1;
                float v2 = acc1[s][n][2] + bb0, v3 = acc1[s][n][3] + bb1;
                v0 = 0.5f * v0 * (1.f + erff(v0 * 0.70710678118654752f));
                v1 = 0.5f * v1 * (1.f + erff(v1 * 0.70710678118654752f));
                v2 = 0.5f * v2 * (1.f + erff(v2 * 0.70710678118654752f));
                v3 = 0.5f * v3 * (1.f + erff(v3 * 0.70710678118654752f));
                sm[OFF_V + row * SA + col]           = v0;
                sm[OFF_V + row * SA + col + 1]       = v1;
                sm[OFF_V + (row + 8) * SA + col]     = v2;
                sm[OFF_V + (row + 8) * SA + col + 1] = v3;
            }
        }
        __syncthreads();            // G complete before gemm2 reads it
        gemm_direct(&sm[OFF_V], wm2 + (size_t)jt * 192 * 192, 192, 0, lane, mi, nj, acc2);
        __syncthreads();            // G consumed before next jt overwrites
    }

    // ---- residual + staged scatter (3 chunks of 64 cols via P) ----
    {
        for (int ch = 0; ch < 3; ch++) {
            #pragma unroll
            for (int s = 0; s < 2; s++) {
                const int row = mi * 32 + s * 16 + gr;
                #pragma unroll
                for (int n = 0; n < 4; n++) {
                    const int col = nj * 32 + n * 8 + 2 * tg;
                    if ((col >> 6) == ch) {
                        const int cl = col & 63;
                        const float bb0 = __ldg(&bm2[col]);
                        const float bb1 = __ldg(&bm2[col + 1]);
                        sm[OFF_P + cl * SP + row]           = acc2[s][n][0] + bb0 + sm[OFF_X + row * SA + col];
                        sm[OFF_P + (cl + 1) * SP + row]     = acc2[s][n][1] + bb1 + sm[OFF_X + row * SA + col + 1];
                        sm[OFF_P + cl * SP + row + 8]       = acc2[s][n][2] + bb0 + sm[OFF_X + (row + 8) * SA + col];
                        sm[OFF_P + (cl + 1) * SP + row + 8] = acc2[s][n][3] + bb1 + sm[OFF_X + (row + 8) * SA + col + 1];
                    }
                }
            }
            __syncthreads();
            for (int l = tid; l < 1024; l += 384) {
                const int cl  = l >> 4;
                const int r16 = l & 15;
                const int ty  = r16 >> 1, half = r16 & 1;
                const int c   = ch * 64 + cl;
                const int sh  = (hb * 8 + ty + 4) & 255;
                const int sw  = (wb * 8 + half * 4 + 4) & 255;
                const float4 v = *(const float4*)&sm[OFF_P + cl * SP + ty * 8 + half * 4];
                *(float4*)&out[(((size_t)(b * 192 + c)) << 16) + (sh << 8) + sw] = v;
            }
            __syncthreads();
        }
    }
}

extern "C" void kernel_launch(void* const* d_in, const int* in_sizes, int n_in,
                              void* d_out, int out_size)
{
    (void)in_sizes; (void)n_in; (void)out_size;
    const float* x    = (const float*)d_in[0];
    const float* g1   = (const float*)d_in[1];
    const float* b1   = (const float*)d_in[2];
    const float* wqkv = (const float*)d_in[3];
    const float* bqkv = (const float*)d_in[4];
    const float* wo   = (const float*)d_in[5];
    const float* bo   = (const float*)d_in[6];
    const float* g2   = (const float*)d_in[7];
    const float* b2   = (const float*)d_in[8];
    const float* wm1  = (const float*)d_in[9];
    const float* bm1  = (const float*)d_in[10];
    const float* wm2  = (const float*)d_in[11];
    const float* bm2  = (const float*)d_in[12];
    float* out = (float*)d_out;

    cudaFuncSetAttribute(swin_block_kernel,
                         cudaFuncAttributeMaxDynamicSharedMemorySize, SMEM_BYTES);
    swin_block_kernel<<<4096, 384, SMEM_BYTES>>>(
        x, g1, b1, wqkv, bqkv, wo, bo, g2, b2, wm1, bm1, wm2, bm2, out);
}